// round 6
// baseline (speedup 1.0000x reference)
#include <cuda_runtime.h>
#include <cuda_fp16.h>
#include <math.h>
#include <stdint.h>

#define BATCH 32
#define TT 4096
#define DD 512
#define MM (BATCH * TT)

#define LDA 520          // A16 smem row stride in halves
#define LDB 136          // B16 smem row stride in halves

// ---------------- device scratch (no allocation allowed) -------------------
__device__ float g_e_t[MM];
__device__ float g_dec[BATCH * DD];
__device__ __half g_Wh16[DD * DD];   // fp16 copy of W_h [k][n]

// ---------------- smem layout (bytes) --------------------------------------
#define SM_A     0                       // 128 * LDA * 2 = 133120
#define SM_B0    133120                  // 32 * LDB * 2 = 8704
#define SM_B1    (SM_B0 + 8704)
#define SM_V     (SM_B1 + 8704)          // float[512]
#define SM_WC    (SM_V + 2048)
#define SM_DEC   (SM_WC + 2048)
#define SM_ESM   (SM_DEC + 2048)         // float[128]
#define SM_TOTAL (SM_ESM + 512 + 512)    // 157696

// ---------------- PTX helpers ----------------------------------------------
__device__ __forceinline__ uint32_t smem_u32(const void* p) {
    uint32_t a;
    asm("{ .reg .u64 t; cvta.to.shared.u64 t, %1; cvt.u32.u64 %0, t; }" : "=r"(a) : "l"(p));
    return a;
}
__device__ __forceinline__ void cp16(uint32_t dst, const void* src) {
    asm volatile("cp.async.cg.shared.global [%0], [%1], 16;" :: "r"(dst), "l"(src));
}
__device__ __forceinline__ void cp_commit() {
    asm volatile("cp.async.commit_group;" ::: "memory");
}
__device__ __forceinline__ void cp_wait1() {
    asm volatile("cp.async.wait_group 1;" ::: "memory");
}
__device__ __forceinline__ void cp_wait0() {
    asm volatile("cp.async.wait_group 0;" ::: "memory");
}
__device__ __forceinline__ float tanhap(float x) {
    float y; asm("tanh.approx.f32 %0, %1;" : "=f"(y) : "f"(x)); return y;
}
__device__ __forceinline__ void ldsm_x4(uint32_t* r, uint32_t addr) {
    asm volatile("ldmatrix.sync.aligned.m8n8.x4.shared.b16 {%0,%1,%2,%3}, [%4];"
                 : "=r"(r[0]), "=r"(r[1]), "=r"(r[2]), "=r"(r[3]) : "r"(addr));
}
__device__ __forceinline__ void ldsm_x4_t(uint32_t* r, uint32_t addr) {
    asm volatile("ldmatrix.sync.aligned.m8n8.x4.trans.shared.b16 {%0,%1,%2,%3}, [%4];"
                 : "=r"(r[0]), "=r"(r[1]), "=r"(r[2]), "=r"(r[3]) : "r"(addr));
}
__device__ __forceinline__ void mma_f16(float* c, const uint32_t* a, const uint32_t* b) {
    asm volatile(
        "mma.sync.aligned.m16n8k16.row.col.f32.f16.f16.f32 "
        "{%0,%1,%2,%3}, {%4,%5,%6,%7}, {%8,%9}, {%0,%1,%2,%3};"
        : "+f"(c[0]), "+f"(c[1]), "+f"(c[2]), "+f"(c[3])
        : "r"(a[0]), "r"(a[1]), "r"(a[2]), "r"(a[3]), "r"(b[0]), "r"(b[1]));
}

// ---------------------------------------------------------------------------
__global__ __launch_bounds__(256) void zero_kernel(float* __restrict__ ctx) {
    int i = blockIdx.x * 256 + threadIdx.x;
    if (i < BATCH * DD) ctx[i] = 0.0f;
}

__global__ __launch_bounds__(256) void prep_wh_kernel(const float* __restrict__ Wh) {
    int i = blockIdx.x * 256 + threadIdx.x;
    g_Wh16[i] = __float2half(Wh[i]);
}

__global__ __launch_bounds__(256) void dec_kernel(
    const float* __restrict__ s, const float* __restrict__ Ws, const float* __restrict__ bs)
{
    int idx = blockIdx.x * 256 + threadIdx.x;
    int b = idx >> 9, e = idx & 511;
    float acc = bs[e];
    const float* sp = s + b * DD;
#pragma unroll 8
    for (int d = 0; d < DD; d++) acc += sp[d] * Ws[d * DD + e];
    g_dec[idx] = acc;
}

// ---------------------------------------------------------------------------
// fp16 tensor-core score GEMM, fused tanh/V-dot epilogue.
// CTA: 128 rows x full N=512 (4 N-blocks of 128), A resident in smem as fp16.
// 512 threads, 16 warps (4 M x 4 N), warp tile 32x32, BK=32 double-buffered B.
// Flat (nb,kt) loop with cross-boundary prefetch.
// ---------------------------------------------------------------------------
__global__ __launch_bounds__(512) void fused_score_gemm(
    const float* __restrict__ h, const float* __restrict__ cov,
    const float* __restrict__ Wc, const float* __restrict__ V)
{
    extern __shared__ char smem[];
    __half* A16 = (__half*)(smem + SM_A);
    float* sV   = (float*)(smem + SM_V);
    float* sWc  = (float*)(smem + SM_WC);
    float* sDec = (float*)(smem + SM_DEC);
    float* eSm  = (float*)(smem + SM_ESM);

    const int tid = threadIdx.x;
    const int lane = tid & 31, wid = tid >> 5;
    const int wm = wid >> 2, wn = wid & 3;           // 4 x 4 warp grid
    const int lr = lane >> 2, lc = lane & 3;
    const int row0 = blockIdx.x * 128;
    const int b = row0 >> 12;

    // epilogue constants + e accumulator init
    if (tid < DD) { sV[tid] = V[tid]; sWc[tid] = Wc[tid]; sDec[tid] = g_dec[b * DD + tid]; }
    if (tid < 128) eSm[tid] = 0.0f;

    // ---- load h rows (fp32) -> convert -> resident fp16 A slab ------------
    {
        const float2* hp = (const float2*)(h + (size_t)row0 * DD);
#pragma unroll
        for (int i = 0; i < 64; i++) {
            int idx2 = tid + i * 512;                // 0..32767
            int m = idx2 >> 8, c2 = idx2 & 255;      // k = 2*c2
            float2 v = hp[(size_t)m * 256 + c2];
            *(__half2*)&A16[m * LDA + 2 * c2] = __floats2half2_rn(v.x, v.y);
        }
    }

    const uint32_t sbB[2] = {smem_u32(smem + SM_B0), smem_u32(smem + SM_B1)};
    const uint32_t sbA = smem_u32(A16);

    // per-row coverage values for this thread's accumulator rows
    float cvr[2][2];
#pragma unroll
    for (int mf = 0; mf < 2; mf++)
#pragma unroll
        for (int h2 = 0; h2 < 2; h2++)
            cvr[mf][h2] = cov[row0 + wm * 32 + mf * 16 + lr + h2 * 8];

    float acc_e[2][2];
    acc_e[0][0] = acc_e[0][1] = acc_e[1][0] = acc_e[1][1] = 0.0f;

    // B tile loader: 32 k-rows x 128 n halves (8KB) = 512 x 16B, 1 per thread
    auto load_b = [&](int stage, int t) {             // t = nb*16 + kt
        int nb = t >> 4, kt = t & 15;
        int k = tid >> 4, n8 = tid & 15;
        cp16(sbB[stage] + (k * LDB + n8 * 8) * 2,
             g_Wh16 + (size_t)(kt * 32 + k) * DD + nb * 128 + n8 * 8);
        cp_commit();
    };

    load_b(0, 0);
    __syncthreads();   // A slab + consts + first B visible ordering point

    float acc[2][4][4];
    for (int t = 0; t < 64; t++) {
        const int kt = t & 15;
        if (kt == 0) {
#pragma unroll
            for (int mf = 0; mf < 2; mf++)
#pragma unroll
                for (int nf = 0; nf < 4; nf++)
#pragma unroll
                    for (int c = 0; c < 4; c++) acc[mf][nf][c] = 0.0f;
        }

        if (t + 1 < 64) { load_b((t + 1) & 1, t + 1); cp_wait1(); }
        else            { cp_wait0(); }
        __syncthreads();

        const uint32_t B = sbB[t & 1];
#pragma unroll
        for (int ks = 0; ks < 2; ks++) {
            const int k0 = kt * 32 + ks * 16;        // global k for A
            uint32_t a[2][4], bb[2][4];
#pragma unroll
            for (int mf = 0; mf < 2; mf++) {
                int row = wm * 32 + mf * 16 + (lane & 15);
                int col = k0 + ((lane >> 4) << 3);
                ldsm_x4(a[mf], sbA + (row * LDA + col) * 2);
            }
#pragma unroll
            for (int p = 0; p < 2; p++) {
                int krow = ks * 16 + (lane & 15);
                int ncol = wn * 32 + p * 16 + ((lane >> 4) << 3);
                ldsm_x4_t(bb[p], B + (krow * LDB + ncol) * 2);
            }
#pragma unroll
            for (int mf = 0; mf < 2; mf++) {
#pragma unroll
                for (int p = 0; p < 2; p++) {
                    mma_f16(acc[mf][2 * p],     a[mf], &bb[p][0]);
                    mma_f16(acc[mf][2 * p + 1], a[mf], &bb[p][2]);
                }
            }
        }
        __syncthreads();

        if (kt == 15) {
            // epilogue for N-block nb: accumulate V . tanh(feat)
            const int nb = t >> 4;
#pragma unroll
            for (int mf = 0; mf < 2; mf++) {
#pragma unroll
                for (int h2 = 0; h2 < 2; h2++) {
                    float cv = cvr[mf][h2];
                    float s = 0.0f;
#pragma unroll
                    for (int nf = 0; nf < 4; nf++) {
#pragma unroll
                        for (int c2 = 0; c2 < 2; c2++) {
                            int nl = nb * 128 + wn * 32 + nf * 8 + 2 * lc + c2;
                            float f = acc[mf][nf][h2 * 2 + c2] + sDec[nl] + cv * sWc[nl];
                            s += sV[nl] * tanhap(f);
                        }
                    }
                    acc_e[mf][h2] += s;
                }
            }
        }
    }

    // reduce across lc quad + wn warps via smem
#pragma unroll
    for (int mf = 0; mf < 2; mf++) {
#pragma unroll
        for (int h2 = 0; h2 < 2; h2++) {
            float s = acc_e[mf][h2];
            s += __shfl_xor_sync(0xffffffffu, s, 1, 4);
            s += __shfl_xor_sync(0xffffffffu, s, 2, 4);
            if (lc == 0)
                atomicAdd(&eSm[wm * 32 + mf * 16 + lr + h2 * 8], s);
        }
    }
    __syncthreads();
    if (tid < 128) g_e_t[row0 + tid] = eSm[tid];
}

// ---------------------------------------------------------------------------
__global__ __launch_bounds__(256) void softmax_kernel(
    const float* __restrict__ cov, float* __restrict__ a_out, float* __restrict__ ncov_out)
{
    int b = blockIdx.x;
    int tid = threadIdx.x;
    const float* e = g_e_t + b * TT;
    __shared__ float red[256];
    float ev[16];
    float m = -1e30f;
#pragma unroll
    for (int k = 0; k < 16; k++) { ev[k] = e[tid + k * 256]; m = fmaxf(m, ev[k]); }
    red[tid] = m; __syncthreads();
    for (int s = 128; s > 0; s >>= 1) {
        if (tid < s) red[tid] = fmaxf(red[tid], red[tid + s]);
        __syncthreads();
    }
    float M = red[0]; __syncthreads();
    float sum = 0.0f;
#pragma unroll
    for (int k = 0; k < 16; k++) { ev[k] = expf(ev[k] - M); sum += ev[k]; }
    red[tid] = sum; __syncthreads();
    for (int s = 128; s > 0; s >>= 1) {
        if (tid < s) red[tid] += red[tid + s];
        __syncthreads();
    }
    float inv = 1.0f / red[0];
#pragma unroll
    for (int k = 0; k < 16; k++) {
        int i = b * TT + tid + k * 256;
        float a = ev[k] * inv;
        a_out[i] = a;
        ncov_out[i] = cov[i] + a;
    }
}

__global__ __launch_bounds__(512) void context_kernel(
    const float* __restrict__ h, const float* __restrict__ a, float* __restrict__ ctx)
{
    int b = blockIdx.x >> 5;
    int tc = blockIdx.x & 31;
    int d = threadIdx.x;
    int t0 = tc * 128;
    const float* hp = h + ((size_t)b * TT + t0) * DD + d;
    const float* ap = a + b * TT + t0;
    float acc = 0.0f;
#pragma unroll 4
    for (int t = 0; t < 128; t++) acc += ap[t] * hp[(size_t)t * DD];
    atomicAdd(&ctx[b * DD + d], acc);
}

// ---------------------------------------------------------------------------
extern "C" void kernel_launch(void* const* d_in, const int* in_sizes, int n_in,
                              void* d_out, int out_size)
{
    const float* h   = (const float*)d_in[0];
    const float* s   = (const float*)d_in[1];
    const float* cov = (const float*)d_in[2];
    const float* Wh  = (const float*)d_in[3];
    const float* Ws  = (const float*)d_in[4];
    const float* bs  = (const float*)d_in[5];
    const float* Wc  = (const float*)d_in[6];
    const float* V   = (const float*)d_in[7];

    float* out   = (float*)d_out;
    float* ctx   = out;
    float* a_out = out + BATCH * DD;
    float* ncov  = a_out + MM;

    cudaFuncSetAttribute(fused_score_gemm,
                         cudaFuncAttributeMaxDynamicSharedMemorySize, SM_TOTAL);

    zero_kernel<<<64, 256>>>(ctx);
    prep_wh_kernel<<<1024, 256>>>(Wh);
    dec_kernel<<<64, 256>>>(s, Ws, bs);
    fused_score_gemm<<<MM / 128, 512, SM_TOTAL>>>(h, cov, Wc, V);
    softmax_kernel<<<BATCH, 256>>>(cov, a_out, ncov);
    context_kernel<<<BATCH * 32, 512>>>(h, a_out, ctx);
}

// round 7
// speedup vs baseline: 1.1977x; 1.1977x over previous
#include <cuda_runtime.h>
#include <cuda_fp16.h>
#include <math.h>
#include <stdint.h>

#define BATCH 32
#define TT 4096
#define DD 512
#define MM (BATCH * TT)

#define LDA 520          // A16 smem row stride in halves (word-stride 260 ≡ 4 mod 32)
#define LDB 264          // B16 smem row stride in halves (word-stride 132 ≡ 4 mod 32)
#define BSTAGE (32 * LDB * 2)   // 16896 bytes per B stage

// ---------------- device scratch (no allocation allowed) -------------------
__device__ float g_e_t[MM];
__device__ float g_dec[BATCH * DD];
__device__ __half g_Wh16[DD * DD];   // fp16 copy of W_h [k][n]

// ---------------- smem layout (bytes) --------------------------------------
#define SM_A     0                          // 128 * LDA * 2 = 133120
#define SM_B     133120                     // 3 stages * 16896 = 50688
#define SM_V     (SM_B + 3 * BSTAGE)        // float[512]
#define SM_WC    (SM_V + 2048)
#define SM_DEC   (SM_WC + 2048)
#define SM_ESM   (SM_DEC + 2048)            // float[128]
#define SM_TOTAL (SM_ESM + 512 + 512)       // ~191 KB

// ---------------- PTX helpers ----------------------------------------------
__device__ __forceinline__ uint32_t smem_u32(const void* p) {
    uint32_t a;
    asm("{ .reg .u64 t; cvta.to.shared.u64 t, %1; cvt.u32.u64 %0, t; }" : "=r"(a) : "l"(p));
    return a;
}
__device__ __forceinline__ void cp16(uint32_t dst, const void* src) {
    asm volatile("cp.async.cg.shared.global [%0], [%1], 16;" :: "r"(dst), "l"(src));
}
__device__ __forceinline__ void cp_commit() {
    asm volatile("cp.async.commit_group;" ::: "memory");
}
__device__ __forceinline__ void cp_wait1() {
    asm volatile("cp.async.wait_group 1;" ::: "memory");
}
__device__ __forceinline__ void cp_wait0() {
    asm volatile("cp.async.wait_group 0;" ::: "memory");
}
__device__ __forceinline__ float tanhap(float x) {
    float y; asm("tanh.approx.f32 %0, %1;" : "=f"(y) : "f"(x)); return y;
}
__device__ __forceinline__ void ldsm_x4(uint32_t* r, uint32_t addr) {
    asm volatile("ldmatrix.sync.aligned.m8n8.x4.shared.b16 {%0,%1,%2,%3}, [%4];"
                 : "=r"(r[0]), "=r"(r[1]), "=r"(r[2]), "=r"(r[3]) : "r"(addr));
}
__device__ __forceinline__ void ldsm_x4_t(uint32_t* r, uint32_t addr) {
    asm volatile("ldmatrix.sync.aligned.m8n8.x4.trans.shared.b16 {%0,%1,%2,%3}, [%4];"
                 : "=r"(r[0]), "=r"(r[1]), "=r"(r[2]), "=r"(r[3]) : "r"(addr));
}
__device__ __forceinline__ void mma_f16(float* c, const uint32_t* a, const uint32_t* b) {
    asm volatile(
        "mma.sync.aligned.m16n8k16.row.col.f32.f16.f16.f32 "
        "{%0,%1,%2,%3}, {%4,%5,%6,%7}, {%8,%9}, {%0,%1,%2,%3};"
        : "+f"(c[0]), "+f"(c[1]), "+f"(c[2]), "+f"(c[3])
        : "r"(a[0]), "r"(a[1]), "r"(a[2]), "r"(a[3]), "r"(b[0]), "r"(b[1]));
}

// ---------------------------------------------------------------------------
__global__ __launch_bounds__(256) void zero_kernel(float* __restrict__ ctx) {
    int i = blockIdx.x * 256 + threadIdx.x;
    if (i < BATCH * DD) ctx[i] = 0.0f;
}

__global__ __launch_bounds__(256) void prep_wh_kernel(const float* __restrict__ Wh) {
    int i = blockIdx.x * 256 + threadIdx.x;
    g_Wh16[i] = __float2half(Wh[i]);
}

__global__ __launch_bounds__(256) void dec_kernel(
    const float* __restrict__ s, const float* __restrict__ Ws, const float* __restrict__ bs)
{
    int idx = blockIdx.x * 256 + threadIdx.x;
    int b = idx >> 9, e = idx & 511;
    float acc = bs[e];
    const float* sp = s + b * DD;
#pragma unroll 8
    for (int d = 0; d < DD; d++) acc += sp[d] * Ws[d * DD + e];
    g_dec[idx] = acc;
}

// ---------------------------------------------------------------------------
// fp16 tensor-core score GEMM, fused tanh/V-dot epilogue.
// CTA: 128 rows x full N=512, A resident fp16 in smem.
// 256 threads, 8 warps (2 M x 4 N), warp tile 64x64 over a 128x256 N-pair.
// B: 32k x 256n per stage, 3-stage cp.async ring, ONE barrier per kt.
// ---------------------------------------------------------------------------
__global__ __launch_bounds__(256) void fused_score_gemm(
    const float* __restrict__ h, const float* __restrict__ cov,
    const float* __restrict__ Wc, const float* __restrict__ V)
{
    extern __shared__ char smem[];
    __half* A16 = (__half*)(smem + SM_A);
    float* sV   = (float*)(smem + SM_V);
    float* sWc  = (float*)(smem + SM_WC);
    float* sDec = (float*)(smem + SM_DEC);
    float* eSm  = (float*)(smem + SM_ESM);

    const int tid = threadIdx.x;
    const int lane = tid & 31, wid = tid >> 5;
    const int wm = wid >> 2, wn = wid & 3;           // 2 x 4 warp grid
    const int lr = lane >> 2, lc = lane & 3;
    const int row0 = blockIdx.x * 128;
    const int b = row0 >> 12;

    for (int i = tid; i < DD; i += 256) {
        sV[i] = V[i]; sWc[i] = Wc[i]; sDec[i] = g_dec[b * DD + i];
    }
    if (tid < 128) eSm[tid] = 0.0f;

    // ---- load h rows (fp32) -> convert -> resident fp16 A slab ------------
    {
        const float2* hp = (const float2*)(h + (size_t)row0 * DD);
#pragma unroll
        for (int i = 0; i < 128; i++) {
            int idx2 = tid + i * 256;
            int m = idx2 >> 8, c2 = idx2 & 255;
            float2 v = hp[(size_t)m * 256 + c2];
            *(__half2*)&A16[m * LDA + 2 * c2] = __floats2half2_rn(v.x, v.y);
        }
    }

    const uint32_t sbA = smem_u32(A16);
    const uint32_t sbB = smem_u32(smem + SM_B);

    float cvr[4][2];
#pragma unroll
    for (int mf = 0; mf < 4; mf++)
#pragma unroll
        for (int h2 = 0; h2 < 2; h2++)
            cvr[mf][h2] = cov[row0 + wm * 64 + mf * 16 + lr + h2 * 8];

    float acc_e[4][2];
#pragma unroll
    for (int mf = 0; mf < 4; mf++) { acc_e[mf][0] = 0.0f; acc_e[mf][1] = 0.0f; }

    // B loader: stage = 32 k-rows x 256 n halves; 1024 cp16 / 256 thr = 4 each
    auto load_b = [&](int t) {                       // t = npair*16 + kt
        const int npair = t >> 4, kt = t & 15;
        const uint32_t dst = sbB + (t % 3) * BSTAGE;
        const __half* src = g_Wh16 + (size_t)(kt * 32) * DD + npair * 256;
#pragma unroll
        for (int i = 0; i < 4; i++) {
            int cid = tid + i * 256;                 // 0..1023
            int k = cid >> 5, c = cid & 31;          // 32 x 16B chunks per row
            cp16(dst + k * (LDB * 2) + c * 16, src + (size_t)k * DD + c * 8);
        }
        cp_commit();
    };

    load_b(0);
    load_b(1);
    __syncthreads();   // A slab + consts + stage fills ordered

    float acc[4][8][4];
    for (int t = 0; t < 32; t++) {
        const int kt = t & 15;
        if (kt == 0) {
#pragma unroll
            for (int mf = 0; mf < 4; mf++)
#pragma unroll
                for (int nf = 0; nf < 8; nf++)
#pragma unroll
                    for (int c = 0; c < 4; c++) acc[mf][nf][c] = 0.0f;
        }

        if (t + 2 < 32) cp_wait1(); else if (t + 1 < 32) cp_wait1(); else cp_wait0();
        __syncthreads();

        const uint32_t B = sbB + (t % 3) * BSTAGE;
#pragma unroll
        for (int ks = 0; ks < 2; ks++) {
            const int k0 = kt * 32 + ks * 16;
            uint32_t a[4][4], bb[4][4];
#pragma unroll
            for (int mf = 0; mf < 4; mf++) {
                int row = wm * 64 + mf * 16 + (lane & 15);
                int col = k0 + ((lane >> 4) << 3);
                ldsm_x4(a[mf], sbA + (row * LDA + col) * 2);
            }
#pragma unroll
            for (int p = 0; p < 4; p++) {
                int krow = ks * 16 + (lane & 15);
                int ncol = wn * 64 + p * 16 + ((lane >> 4) << 3);
                ldsm_x4_t(bb[p], B + (krow * LDB + ncol) * 2);
            }
#pragma unroll
            for (int mf = 0; mf < 4; mf++) {
#pragma unroll
                for (int p = 0; p < 4; p++) {
                    mma_f16(acc[mf][2 * p],     a[mf], &bb[p][0]);
                    mma_f16(acc[mf][2 * p + 1], a[mf], &bb[p][2]);
                }
            }
        }

        if (kt == 15) {
            // epilogue for this 256-col N-pair
            const int npair = t >> 4;
#pragma unroll
            for (int mf = 0; mf < 4; mf++) {
#pragma unroll
                for (int h2 = 0; h2 < 2; h2++) {
                    float cv = cvr[mf][h2];
                    float s = 0.0f;
#pragma unroll
                    for (int nf = 0; nf < 8; nf++) {
#pragma unroll
                        for (int c2 = 0; c2 < 2; c2++) {
                            int nl = npair * 256 + wn * 64 + nf * 8 + 2 * lc + c2;
                            float f = acc[mf][nf][h2 * 2 + c2] + sDec[nl] + cv * sWc[nl];
                            s += sV[nl] * tanhap(f);
                        }
                    }
                    acc_e[mf][h2] += s;
                }
            }
        }

        // issue next stage AFTER compute: all warps passed this iter's barrier,
        // so nobody still reads stage (t+2)%3 == (t-1)%3.
        if (t + 2 < 32) load_b(t + 2);
    }

    // reduce across lc quad, then across wn warps via smem atomics
#pragma unroll
    for (int mf = 0; mf < 4; mf++) {
#pragma unroll
        for (int h2 = 0; h2 < 2; h2++) {
            float s = acc_e[mf][h2];
            s += __shfl_xor_sync(0xffffffffu, s, 1, 4);
            s += __shfl_xor_sync(0xffffffffu, s, 2, 4);
            if (lc == 0)
                atomicAdd(&eSm[wm * 64 + mf * 16 + lr + h2 * 8], s);
        }
    }
    __syncthreads();
    if (tid < 128) g_e_t[row0 + tid] = eSm[tid];
}

// ---------------------------------------------------------------------------
__global__ __launch_bounds__(256) void softmax_kernel(
    const float* __restrict__ cov, float* __restrict__ a_out, float* __restrict__ ncov_out)
{
    int b = blockIdx.x;
    int tid = threadIdx.x;
    const float* e = g_e_t + b * TT;
    __shared__ float red[256];
    float ev[16];
    float m = -1e30f;
#pragma unroll
    for (int k = 0; k < 16; k++) { ev[k] = e[tid + k * 256]; m = fmaxf(m, ev[k]); }
    red[tid] = m; __syncthreads();
    for (int s = 128; s > 0; s >>= 1) {
        if (tid < s) red[tid] = fmaxf(red[tid], red[tid + s]);
        __syncthreads();
    }
    float M = red[0]; __syncthreads();
    float sum = 0.0f;
#pragma unroll
    for (int k = 0; k < 16; k++) { ev[k] = expf(ev[k] - M); sum += ev[k]; }
    red[tid] = sum; __syncthreads();
    for (int s = 128; s > 0; s >>= 1) {
        if (tid < s) red[tid] += red[tid + s];
        __syncthreads();
    }
    float inv = 1.0f / red[0];
#pragma unroll
    for (int k = 0; k < 16; k++) {
        int i = b * TT + tid + k * 256;
        float a = ev[k] * inv;
        a_out[i] = a;
        ncov_out[i] = cov[i] + a;
    }
}

__global__ __launch_bounds__(512) void context_kernel(
    const float* __restrict__ h, const float* __restrict__ a, float* __restrict__ ctx)
{
    int b = blockIdx.x >> 5;
    int tc = blockIdx.x & 31;
    int d = threadIdx.x;
    int t0 = tc * 128;
    const float* hp = h + ((size_t)b * TT + t0) * DD + d;
    const float* ap = a + b * TT + t0;
    float acc = 0.0f;
#pragma unroll 4
    for (int t = 0; t < 128; t++) acc += ap[t] * hp[(size_t)t * DD];
    atomicAdd(&ctx[b * DD + d], acc);
}

// ---------------------------------------------------------------------------
extern "C" void kernel_launch(void* const* d_in, const int* in_sizes, int n_in,
                              void* d_out, int out_size)
{
    const float* h   = (const float*)d_in[0];
    const float* s   = (const float*)d_in[1];
    const float* cov = (const float*)d_in[2];
    const float* Wh  = (const float*)d_in[3];
    const float* Ws  = (const float*)d_in[4];
    const float* bs  = (const float*)d_in[5];
    const float* Wc  = (const float*)d_in[6];
    const float* V   = (const float*)d_in[7];

    float* out   = (float*)d_out;
    float* ctx   = out;
    float* a_out = out + BATCH * DD;
    float* ncov  = a_out + MM;

    cudaFuncSetAttribute(fused_score_gemm,
                         cudaFuncAttributeMaxDynamicSharedMemorySize, SM_TOTAL);

    zero_kernel<<<64, 256>>>(ctx);
    prep_wh_kernel<<<1024, 256>>>(Wh);
    dec_kernel<<<64, 256>>>(s, Ws, bs);
    fused_score_gemm<<<MM / 128, 256, SM_TOTAL>>>(h, cov, Wc, V);
    softmax_kernel<<<BATCH, 256>>>(cov, a_out, ncov);
    context_kernel<<<BATCH * 32, 512>>>(h, a_out, ctx);
}

// round 9
// speedup vs baseline: 1.2184x; 1.0172x over previous
#include <cuda_runtime.h>
#include <cuda_fp16.h>
#include <math.h>
#include <stdint.h>

#define BATCH 32
#define TT 4096
#define DD 512
#define MM (BATCH * TT)

#define CTAROWS 64
#define LDA 520          // A16 smem row stride in halves (word stride 260 ≡ 4 mod 32)
#define LDB 264          // B16 smem row stride in halves (word stride 132 ≡ 4 mod 32)
#define BSTAGE (32 * LDB * 2)   // 16896 bytes per B stage (32k x 256n)

// ---------------- device scratch (no allocation allowed) -------------------
__device__ float g_e_t[MM];
__device__ float g_dec[BATCH * DD];
__device__ __half g_Wh16[DD * DD];   // fp16 copy of W_h [k][n]

// ---------------- smem layout (bytes) --------------------------------------
#define SM_A     0                          // 64 * LDA * 2 = 66560
#define SM_B     66560                      // 2 stages * 16896 = 33792
#define SM_V     (SM_B + 2 * BSTAGE)        // float[512]
#define SM_WC    (SM_V + 2048)
#define SM_DEC   (SM_WC + 2048)
#define SM_ESM   (SM_DEC + 2048)            // float[64]
#define SM_TOTAL (SM_ESM + 256 + 256)       // 107008 -> 2 CTAs/SM

// ---------------- PTX helpers ----------------------------------------------
__device__ __forceinline__ uint32_t smem_u32(const void* p) {
    uint32_t a;
    asm("{ .reg .u64 t; cvta.to.shared.u64 t, %1; cvt.u32.u64 %0, t; }" : "=r"(a) : "l"(p));
    return a;
}
__device__ __forceinline__ void cp16(uint32_t dst, const void* src) {
    asm volatile("cp.async.cg.shared.global [%0], [%1], 16;" :: "r"(dst), "l"(src));
}
__device__ __forceinline__ void cp_commit() {
    asm volatile("cp.async.commit_group;" ::: "memory");
}
__device__ __forceinline__ void cp_wait1() {
    asm volatile("cp.async.wait_group 1;" ::: "memory");
}
__device__ __forceinline__ void cp_wait0() {
    asm volatile("cp.async.wait_group 0;" ::: "memory");
}
__device__ __forceinline__ float tanhap(float x) {
    float y; asm("tanh.approx.f32 %0, %1;" : "=f"(y) : "f"(x)); return y;
}
__device__ __forceinline__ void ldsm_x4(uint32_t* r, uint32_t addr) {
    asm volatile("ldmatrix.sync.aligned.m8n8.x4.shared.b16 {%0,%1,%2,%3}, [%4];"
                 : "=r"(r[0]), "=r"(r[1]), "=r"(r[2]), "=r"(r[3]) : "r"(addr));
}
__device__ __forceinline__ void ldsm_x4_t(uint32_t* r, uint32_t addr) {
    asm volatile("ldmatrix.sync.aligned.m8n8.x4.trans.shared.b16 {%0,%1,%2,%3}, [%4];"
                 : "=r"(r[0]), "=r"(r[1]), "=r"(r[2]), "=r"(r[3]) : "r"(addr));
}
__device__ __forceinline__ void mma_f16(float* c, const uint32_t* a, const uint32_t* b) {
    asm volatile(
        "mma.sync.aligned.m16n8k16.row.col.f32.f16.f16.f32 "
        "{%0,%1,%2,%3}, {%4,%5,%6,%7}, {%8,%9}, {%0,%1,%2,%3};"
        : "+f"(c[0]), "+f"(c[1]), "+f"(c[2]), "+f"(c[3])
        : "r"(a[0]), "r"(a[1]), "r"(a[2]), "r"(a[3]), "r"(b[0]), "r"(b[1]));
}

// ---------------------------------------------------------------------------
__global__ __launch_bounds__(256) void zero_kernel(float* __restrict__ ctx) {
    int i = blockIdx.x * 256 + threadIdx.x;
    if (i < BATCH * DD) ctx[i] = 0.0f;
}

__global__ __launch_bounds__(256) void prep_wh_kernel(const float* __restrict__ Wh) {
    int i = blockIdx.x * 256 + threadIdx.x;
    g_Wh16[i] = __float2half(Wh[i]);
}

__global__ __launch_bounds__(256) void dec_kernel(
    const float* __restrict__ s, const float* __restrict__ Ws, const float* __restrict__ bs)
{
    int idx = blockIdx.x * 256 + threadIdx.x;
    int b = idx >> 9, e = idx & 511;
    float acc = bs[e];
    const float* sp = s + b * DD;
#pragma unroll 8
    for (int d = 0; d < DD; d++) acc += sp[d] * Ws[d * DD + e];
    g_dec[idx] = acc;
}

// ---------------------------------------------------------------------------
// fp16 tensor-core score GEMM, fused tanh/V-dot epilogue.
// CTA: 64 rows x full N=512 (2 npairs of 256), A resident fp16 in smem.
// 256 threads, 8 warps (1 M x 8 N), warp tile 64x32. ~105KB smem -> 2 CTAs/SM.
// ---------------------------------------------------------------------------
__global__ __launch_bounds__(256) void fused_score_gemm(
    const float* __restrict__ h, const float* __restrict__ cov,
    const float* __restrict__ Wc, const float* __restrict__ V)
{
    extern __shared__ char smem[];
    __half* A16 = (__half*)(smem + SM_A);
    float* sV   = (float*)(smem + SM_V);
    float* sWc  = (float*)(smem + SM_WC);
    float* sDec = (float*)(smem + SM_DEC);
    float* eSm  = (float*)(smem + SM_ESM);

    const int tid = threadIdx.x;
    const int lane = tid & 31, wn = tid >> 5;        // 8 warps across N
    const int lr = lane >> 2, lc = lane & 3;
    const int row0 = blockIdx.x * CTAROWS;
    const int b = row0 >> 12;

    for (int i = tid; i < DD; i += 256) {
        sV[i] = V[i]; sWc[i] = Wc[i]; sDec[i] = g_dec[b * DD + i];
    }
    if (tid < CTAROWS) eSm[tid] = 0.0f;

    // ---- load h rows (fp32) -> convert -> resident fp16 A slab ------------
    {
        const float2* hp = (const float2*)(h + (size_t)row0 * DD);
#pragma unroll
        for (int i = 0; i < 64; i++) {
            int idx2 = tid + i * 256;                // 0..16383
            int m = idx2 >> 8, c2 = idx2 & 255;      // row m, k = 2*c2
            float2 v = hp[(size_t)m * 256 + c2];
            *(__half2*)&A16[m * LDA + 2 * c2] = __floats2half2_rn(v.x, v.y);
        }
    }

    const uint32_t sbA = smem_u32(A16);
    const uint32_t sbB = smem_u32(smem + SM_B);

    float cvr[4][2];
#pragma unroll
    for (int mf = 0; mf < 4; mf++)
#pragma unroll
        for (int h2 = 0; h2 < 2; h2++)
            cvr[mf][h2] = cov[row0 + mf * 16 + lr + h2 * 8];

    float acc_e[4][2];
#pragma unroll
    for (int mf = 0; mf < 4; mf++) { acc_e[mf][0] = 0.0f; acc_e[mf][1] = 0.0f; }

    // B loader: stage = 32 k-rows x 256 n halves; 1024 x 16B / 256 thr = 4 ea
    auto load_b = [&](int stage, int t) {            // t = npair*16 + kt
        const int npair = t >> 4, kt = t & 15;
        const uint32_t dst = sbB + stage * BSTAGE;
        const __half* src = g_Wh16 + (size_t)(kt * 32) * DD + npair * 256;
#pragma unroll
        for (int i = 0; i < 4; i++) {
            int cid = tid + i * 256;                 // 0..1023
            int k = cid >> 5, c = cid & 31;
            cp16(dst + k * (LDB * 2) + c * 16, src + (size_t)k * DD + c * 8);
        }
        cp_commit();
    };

    load_b(0, 0);
    __syncthreads();   // A slab + consts + stage0 ordering

    float acc[4][4][4];
    for (int t = 0; t < 32; t++) {
        const int kt = t & 15;
        if (kt == 0) {
#pragma unroll
            for (int mf = 0; mf < 4; mf++)
#pragma unroll
                for (int nf = 0; nf < 4; nf++)
#pragma unroll
                    for (int c = 0; c < 4; c++) acc[mf][nf][c] = 0.0f;
        }

        if (t + 1 < 32) { load_b((t + 1) & 1, t + 1); cp_wait1(); }
        else            { cp_wait0(); }
        __syncthreads();

        const uint32_t B = sbB + (t & 1) * BSTAGE;
#pragma unroll
        for (int ks = 0; ks < 2; ks++) {
            const int k0 = kt * 32 + ks * 16;
            uint32_t a[4][4], bb[2][4];
#pragma unroll
            for (int mf = 0; mf < 4; mf++) {
                int row = mf * 16 + (lane & 15);
                int col = k0 + ((lane >> 4) << 3);
                ldsm_x4(a[mf], sbA + (row * LDA + col) * 2);
            }
#pragma unroll
            for (int p = 0; p < 2; p++) {
                int krow = ks * 16 + (lane & 15);
                int ncol = wn * 32 + p * 16 + ((lane >> 4) << 3);
                ldsm_x4_t(bb[p], B + (krow * LDB + ncol) * 2);
            }
#pragma unroll
            for (int mf = 0; mf < 4; mf++) {
#pragma unroll
                for (int p = 0; p < 2; p++) {
                    mma_f16(acc[mf][2 * p],     a[mf], &bb[p][0]);
                    mma_f16(acc[mf][2 * p + 1], a[mf], &bb[p][2]);
                }
            }
        }
        __syncthreads();

        if (kt == 15) {
            // epilogue for this 256-col npair
            const int npair = t >> 4;
#pragma unroll
            for (int mf = 0; mf < 4; mf++) {
#pragma unroll
                for (int h2 = 0; h2 < 2; h2++) {
                    float cv = cvr[mf][h2];
                    float s = 0.0f;
#pragma unroll
                    for (int nf = 0; nf < 4; nf++) {
#pragma unroll
                        for (int c2 = 0; c2 < 2; c2++) {
                            int nl = npair * 256 + wn * 32 + nf * 8 + 2 * lc + c2;
                            float f = acc[mf][nf][h2 * 2 + c2] + sDec[nl] + cv * sWc[nl];
                            s += sV[nl] * tanhap(f);
                        }
                    }
                    acc_e[mf][h2] += s;
                }
            }
        }
    }

    // reduce: lc quad shuffle, then across the 8 wn warps via smem atomics
#pragma unroll
    for (int mf = 0; mf < 4; mf++) {
#pragma unroll
        for (int h2 = 0; h2 < 2; h2++) {
            float s = acc_e[mf][h2];
            s += __shfl_xor_sync(0xffffffffu, s, 1, 4);
            s += __shfl_xor_sync(0xffffffffu, s, 2, 4);
            if (lc == 0)
                atomicAdd(&eSm[mf * 16 + lr + h2 * 8], s);
        }
    }
    __syncthreads();
    if (tid < CTAROWS) g_e_t[row0 + tid] = eSm[tid];
}

// ---------------------------------------------------------------------------
__global__ __launch_bounds__(256) void softmax_kernel(
    const float* __restrict__ cov, float* __restrict__ a_out, float* __restrict__ ncov_out)
{
    int b = blockIdx.x;
    int tid = threadIdx.x;
    const float* e = g_e_t + b * TT;
    __shared__ float red[256];
    float ev[16];
    float m = -1e30f;
#pragma unroll
    for (int k = 0; k < 16; k++) { ev[k] = e[tid + k * 256]; m = fmaxf(m, ev[k]); }
    red[tid] = m; __syncthreads();
    for (int s = 128; s > 0; s >>= 1) {
        if (tid < s) red[tid] = fmaxf(red[tid], red[tid + s]);
        __syncthreads();
    }
    float M = red[0]; __syncthreads();
    float sum = 0.0f;
#pragma unroll
    for (int k = 0; k < 16; k++) { ev[k] = expf(ev[k] - M); sum += ev[k]; }
    red[tid] = sum; __syncthreads();
    for (int s = 128; s > 0; s >>= 1) {
        if (tid < s) red[tid] += red[tid + s];
        __syncthreads();
    }
    float inv = 1.0f / red[0];
#pragma unroll
    for (int k = 0; k < 16; k++) {
        int i = b * TT + tid + k * 256;
        float a = ev[k] * inv;
        a_out[i] = a;
        ncov_out[i] = cov[i] + a;
    }
}

__global__ __launch_bounds__(512) void context_kernel(
    const float* __restrict__ h, const float* __restrict__ a, float* __restrict__ ctx)
{
    int b = blockIdx.x >> 5;
    int tc = blockIdx.x & 31;
    int d = threadIdx.x;
    int t0 = tc * 128;
    const float* hp = h + ((size_t)b * TT + t0) * DD + d;
    const float* ap = a + b * TT + t0;
    float acc = 0.0f;
#pragma unroll 4
    for (int t = 0; t < 128; t++) acc += ap[t] * hp[(size_t)t * DD];
    atomicAdd(&ctx[b * DD + d], acc);
}

// ---------------------------------------------------------------------------
extern "C" void kernel_launch(void* const* d_in, const int* in_sizes, int n_in,
                              void* d_out, int out_size)
{
    const float* h   = (const float*)d_in[0];
    const float* s   = (const float*)d_in[1];
    const float* cov = (const float*)d_in[2];
    const float* Wh  = (const float*)d_in[3];
    const float* Ws  = (const float*)d_in[4];
    const float* bs  = (const float*)d_in[5];
    const float* Wc  = (const float*)d_in[6];
    const float* V   = (const float*)d_in[7];

    float* out   = (float*)d_out;
    float* ctx   = out;
    float* a_out = out + BATCH * DD;
    float* ncov  = a_out + MM;

    cudaFuncSetAttribute(fused_score_gemm,
                         cudaFuncAttributeMaxDynamicSharedMemorySize, SM_TOTAL);

    zero_kernel<<<64, 256>>>(ctx);
    prep_wh_kernel<<<1024, 256>>>(Wh);
    dec_kernel<<<64, 256>>>(s, Ws, bs);
    fused_score_gemm<<<MM / CTAROWS, 256, SM_TOTAL>>>(h, cov, Wc, V);
    softmax_kernel<<<BATCH, 256>>>(cov, a_out, ncov);
    context_kernel<<<BATCH * 32, 512>>>(h, a_out, ctx);
}